// round 2
// baseline (speedup 1.0000x reference)
#include <cuda_runtime.h>
#include <cstdint>

// Output: [B=16, T=50, H=100, W=100, P=25] fp32 = 200M elems = 800MB.
// Single fused kernel: HBM-saturating zero fill (STG.128) + last-block-done
// scatter of 20k ones. Saves the second kernel launch + gap (~7us).

static constexpr int B = 16;
static constexpr int T = 50;
static constexpr int H = 100;
static constexpr int W = 100;
static constexpr int P = 25;
static constexpr int NPTS = B * T * P;   // 20000

__device__ unsigned int g_done_counter = 0;

__global__ void fused_raster_kernel(const float* __restrict__ x,
                                    const float* __restrict__ resolution,
                                    const float* __restrict__ origin,
                                    float* __restrict__ out,
                                    long long n_vec4,
                                    unsigned int total_blocks) {
    // ---- Phase 1: zero this block's vec4 slice (128-bit stores) ----
    long long i = (long long)blockIdx.x * blockDim.x + threadIdx.x;
    if (i < n_vec4) {
        reinterpret_cast<float4*>(out)[i] = make_float4(0.f, 0.f, 0.f, 0.f);
    }

    // ---- Phase 2: last-finishing block performs the scatter ----
    __syncthreads();

    __shared__ bool s_is_last;
    if (threadIdx.x == 0) {
        // Release: make this block's zero stores visible before the count bump.
        __threadfence();
        unsigned int prev = atomicAdd(&g_done_counter, 1u);
        s_is_last = (prev == total_blocks - 1u);
    }
    __syncthreads();

    if (!s_is_last) return;

    // Acquire: ensure we observe every block's zero stores before overwriting.
    __threadfence();

    // 20000 points over 256 threads -> ~78 independent iterations each (high MLP).
    for (int gid = threadIdx.x; gid < NPTS; gid += blockDim.x) {
        int p  = gid % P;
        int bt = gid / P;                     // b*T + t

        const float px = x[bt * (2 * P) + 2 * p + 0];   // x -> col
        const float py = x[bt * (2 * P) + 2 * p + 1];   // y -> row
        const float rx = resolution[bt * 2 + 0];
        const float ry = resolution[bt * 2 + 1];
        const float ox = origin[bt * 2 + 0];
        const float oy = origin[bt * 2 + 1];

        int col = (int)(px / rx + ox);        // trunc toward zero == astype(int)
        int row = (int)(py / ry + oy);

        if (row < 0 || row >= H || col < 0 || col >= W) continue;  // JAX drops OOB

        long long off = ((((long long)bt) * H + row) * W + col) * P + p;
        out[off] = 1.0f;
    }

    // Reset counter for the next graph replay (only this block touches it now).
    if (threadIdx.x == 0) {
        __threadfence();
        g_done_counter = 0u;
    }
}

// ---------------------------------------------------------------------------
extern "C" void kernel_launch(void* const* d_in, const int* in_sizes, int n_in,
                              void* d_out, int out_size) {
    const float* x          = (const float*)d_in[0];
    const float* resolution = (const float*)d_in[1];
    const float* origin     = (const float*)d_in[2];
    float* out = (float*)d_out;

    const long long n = (long long)out_size;          // 200,000,000 (divisible by 4)
    const long long n_vec4 = n / 4;                   // 50,000,000

    const int threads = 256;
    const unsigned int blocks = (unsigned int)((n_vec4 + threads - 1) / threads);

    fused_raster_kernel<<<blocks, threads>>>(x, resolution, origin, out,
                                             n_vec4, blocks);
}

// round 3
// speedup vs baseline: 2.6068x; 2.6068x over previous
#include <cuda_runtime.h>
#include <cstdint>

// Output: [B=16, T=50, H=100, W=100, P=25] fp32 = 200M elems = 800MB.
// Two kernels: streaming zero-fill (4x STG.128.CS per thread) + tiny scatter.

static constexpr int B = 16;
static constexpr int T = 50;
static constexpr int H = 100;
static constexpr int W = 100;
static constexpr int P = 25;
static constexpr int NPTS = B * T * P;   // 20000

// ---------------------------------------------------------------------------
// Kernel 1: zero fill. Each thread writes 4 float4 (64B) with evict-first
// streaming stores; warp covers 4x contiguous 4KB-ish stripes (coalesced).
// n_vec4 = 50,000,000; VPT=4 -> 12,500,000 thread-slots -> 48829 blocks @256.
// ---------------------------------------------------------------------------
static constexpr int VPT = 4;  // float4s per thread

__global__ void zero_kernel(float4* __restrict__ out, long long n_vec4) {
    const float4 z = make_float4(0.f, 0.f, 0.f, 0.f);
    long long base = (long long)blockIdx.x * (blockDim.x * VPT) + threadIdx.x;
#pragma unroll
    for (int k = 0; k < VPT; k++) {
        long long i = base + (long long)k * blockDim.x;
        if (i < n_vec4) {
            __stcs(&out[i], z);   // streaming store: evict-first, smooth writeback
        }
    }
}

// ---------------------------------------------------------------------------
// Kernel 2: scatter 1.0f at (b, t, row, col, p).
//   points = x.reshape(B,T,P,2); col = pt[...,0], row = pt[...,1]
//   idx = (int)(pt / resolution + origin)  (trunc; matches astype for inputs)
// ---------------------------------------------------------------------------
__global__ void scatter_kernel(const float2* __restrict__ x,     // [B*T*P] pairs
                               const float2* __restrict__ resolution, // [B*T]
                               const float2* __restrict__ origin,     // [B*T]
                               float* __restrict__ out) {
    int gid = blockIdx.x * blockDim.x + threadIdx.x;   // over B*T*P = 20000
    if (gid >= NPTS) return;

    int p  = gid % P;
    int bt = gid / P;          // b*T + t

    const float2 pt = __ldg(&x[gid]);          // (px, py), 8B aligned
    const float2 rs = __ldg(&resolution[bt]);  // (rx, ry)
    const float2 og = __ldg(&origin[bt]);      // (ox, oy)

    int col = (int)(pt.x / rs.x + og.x);
    int row = (int)(pt.y / rs.y + og.y);

    // JAX .at[].set drops out-of-bounds scatter updates; mirror that.
    if (row < 0 || row >= H || col < 0 || col >= W) return;

    long long off = ((((long long)bt) * H + row) * W + col) * P + p;
    out[off] = 1.0f;
}

// ---------------------------------------------------------------------------
extern "C" void kernel_launch(void* const* d_in, const int* in_sizes, int n_in,
                              void* d_out, int out_size) {
    const float2* x          = (const float2*)d_in[0];
    const float2* resolution = (const float2*)d_in[1];
    const float2* origin     = (const float2*)d_in[2];
    float* out = (float*)d_out;

    const long long n = (long long)out_size;          // 200,000,000 (div by 4)
    const long long n_vec4 = n / 4;                   // 50,000,000

    {
        const int threads = 256;
        const long long slots = (n_vec4 + VPT - 1) / VPT;
        const unsigned blocks = (unsigned)((slots + threads - 1) / threads);
        zero_kernel<<<blocks, threads>>>((float4*)out, n_vec4);
    }
    {
        const int threads = 256;
        const int blocks = (NPTS + threads - 1) / threads;   // 79
        scatter_kernel<<<blocks, threads>>>(x, resolution, origin, out);
    }
}

// round 4
// speedup vs baseline: 2.6307x; 1.0092x over previous
#include <cuda_runtime.h>
#include <cstdint>

// Output: [B=16, T=50, H=100, W=100, P=25] fp32 = 200M elems = 800MB.
// Kernel 1: HBM-saturating zero fill; its first 79 blocks ALSO precompute the
//           20k scatter offsets into a device scratch array (disjoint from out,
//           so no ordering hazard, no fences).
// Kernel 2: tiny commit — load offset (L2-hot) -> store 1.0f. Minimal tail.

static constexpr int B = 16;
static constexpr int T = 50;
static constexpr int H = 100;
static constexpr int W = 100;
static constexpr int P = 25;
static constexpr int NPTS = B * T * P;   // 20000

static constexpr int VPT = 4;            // float4s per thread in zero fill
static constexpr int ZTHREADS = 256;
static constexpr int PREP_BLOCKS = (NPTS + ZTHREADS - 1) / ZTHREADS;  // 79

__device__ int g_offsets[NPTS];          // precomputed word offsets (-1 = OOB)

// ---------------------------------------------------------------------------
__global__ void zero_and_prep_kernel(const float2* __restrict__ x,          // [B*T*P] (px,py)
                                     const float2* __restrict__ resolution, // [B*T]
                                     const float2* __restrict__ origin,     // [B*T]
                                     float4* __restrict__ out,
                                     long long n_vec4) {
    // ---- Prep (first 79 blocks only; writes scratch, never touches out) ----
    if (blockIdx.x < PREP_BLOCKS) {
        int gid = blockIdx.x * blockDim.x + threadIdx.x;
        if (gid < NPTS) {
            int p  = gid % P;
            int bt = gid / P;

            const float2 pt = __ldg(&x[gid]);
            const float2 rs = __ldg(&resolution[bt]);
            const float2 og = __ldg(&origin[bt]);

            int col = (int)(pt.x / rs.x + og.x);   // trunc == astype(int)
            int row = (int)(pt.y / rs.y + og.y);

            int off = -1;
            if (row >= 0 && row < H && col >= 0 && col < W) {
                long long o = ((((long long)bt) * H + row) * W + col) * P + p;
                off = (int)o;                      // 200M < 2^31, fits
            }
            g_offsets[gid] = off;
        }
    }

    // ---- Zero fill: 4x STG.128 streaming stores per thread ----
    const float4 z = make_float4(0.f, 0.f, 0.f, 0.f);
    long long base = (long long)blockIdx.x * (blockDim.x * VPT) + threadIdx.x;
#pragma unroll
    for (int k = 0; k < VPT; k++) {
        long long i = base + (long long)k * blockDim.x;
        if (i < n_vec4) {
            __stcs(&out[i], z);
        }
    }
}

// ---------------------------------------------------------------------------
__global__ void commit_kernel(float* __restrict__ out) {
    int gid = blockIdx.x * blockDim.x + threadIdx.x;
    if (gid >= NPTS) return;
    int off = __ldcg(&g_offsets[gid]);   // L2-hot (written moments ago)
    if (off >= 0) out[off] = 1.0f;       // JAX drops OOB updates
}

// ---------------------------------------------------------------------------
extern "C" void kernel_launch(void* const* d_in, const int* in_sizes, int n_in,
                              void* d_out, int out_size) {
    const float2* x          = (const float2*)d_in[0];
    const float2* resolution = (const float2*)d_in[1];
    const float2* origin     = (const float2*)d_in[2];
    float* out = (float*)d_out;

    const long long n = (long long)out_size;      // 200,000,000 (div by 4)
    const long long n_vec4 = n / 4;               // 50,000,000

    {
        const long long slots = (n_vec4 + VPT - 1) / VPT;
        const unsigned blocks = (unsigned)((slots + ZTHREADS - 1) / ZTHREADS);
        zero_and_prep_kernel<<<blocks, ZTHREADS>>>(x, resolution, origin,
                                                   (float4*)out, n_vec4);
    }
    {
        const int threads = 256;
        const int blocks = (NPTS + threads - 1) / threads;   // 79
        commit_kernel<<<blocks, threads>>>(out);
    }
}

// round 5
// speedup vs baseline: 2.7171x; 1.0329x over previous
#include <cuda_runtime.h>
#include <cstdint>

// Output: [B=16, T=50, H=100, W=100, P=25] fp32 = 200M elems = 800MB.
// SINGLE kernel. Each block zeroes a contiguous 4096-float slice (4x STG.128
// streaming), then __syncthreads (CTA-scope order, no global fence), then
// warps 0-1 recompute the <=50 candidate points of the <=2 bt-regions that
// overlap this slice and write 1.0f for any landing inside the slice.
// Exactly-once, race-free: every output offset belongs to exactly one slice.

static constexpr int B = 16;
static constexpr int T = 50;
static constexpr int H = 100;
static constexpr int W = 100;
static constexpr int P = 25;
static constexpr long long BT_STRIDE = (long long)H * W * P;  // 250000 elems per bt

static constexpr int VPT = 4;                       // float4s per thread
static constexpr int ZTHREADS = 256;
static constexpr int SLICE = ZTHREADS * VPT * 4;    // 4096 floats per block

__global__ void fused_raster_kernel(const float2* __restrict__ x,          // [B*T*P] (px,py)
                                    const float2* __restrict__ resolution, // [B*T]
                                    const float2* __restrict__ origin,     // [B*T]
                                    float* __restrict__ out,
                                    long long n_vec4) {
    // ---- Phase 1: zero this block's slice (4x STG.128, evict-first) ----
    const float4 z = make_float4(0.f, 0.f, 0.f, 0.f);
    long long base = (long long)blockIdx.x * (ZTHREADS * VPT) + threadIdx.x;
#pragma unroll
    for (int k = 0; k < VPT; k++) {
        long long i = base + (long long)k * ZTHREADS;
        if (i < n_vec4) {
            __stcs(reinterpret_cast<float4*>(out) + i, z);
        }
    }

    // CTA-scope ordering: this block's zeros land before its ones. Cheap (BAR).
    __syncthreads();

    // ---- Phase 2: ones for offsets inside [s, e) ----
    const long long n = n_vec4 * 4;
    const long long s = (long long)blockIdx.x * SLICE;
    const long long e = (s + SLICE < n) ? (s + SLICE) : n;

    const int bt0 = (int)(s / BT_STRIDE);            // slice spans <= 2 bt regions
    const int bt1 = (int)((e - 1) / BT_STRIDE);
    const int nbt = bt1 - bt0 + 1;                   // 1 or 2

    const int w = threadIdx.x >> 5;                  // warp id
    const int l = threadIdx.x & 31;                  // lane id
    if (w < nbt && l < P) {
        const int bt = bt0 + w;                      // bt1 <= B*T-1 by construction
        const float2 pt = __ldg(&x[bt * P + l]);     // (px, py)
        const float2 rs = __ldg(&resolution[bt]);
        const float2 og = __ldg(&origin[bt]);

        const int col = (int)(pt.x / rs.x + og.x);   // trunc == astype(int)
        const int row = (int)(pt.y / rs.y + og.y);

        if (row >= 0 && row < H && col >= 0 && col < W) {   // JAX drops OOB
            const long long off =
                (((long long)bt * H + row) * W + col) * P + l;
            if (off >= s && off < e) {
                out[off] = 1.0f;
            }
        }
    }
}

// ---------------------------------------------------------------------------
extern "C" void kernel_launch(void* const* d_in, const int* in_sizes, int n_in,
                              void* d_out, int out_size) {
    const float2* x          = (const float2*)d_in[0];
    const float2* resolution = (const float2*)d_in[1];
    const float2* origin     = (const float2*)d_in[2];
    float* out = (float*)d_out;

    const long long n = (long long)out_size;         // 200,000,000 (div by 4)
    const long long n_vec4 = n / 4;                  // 50,000,000

    const long long slots = (n_vec4 + VPT - 1) / VPT;
    const unsigned blocks = (unsigned)((slots + ZTHREADS - 1) / ZTHREADS);  // 48829

    fused_raster_kernel<<<blocks, ZTHREADS>>>(x, resolution, origin, out, n_vec4);
}